// round 17
// baseline (speedup 1.0000x reference)
#include <cuda_runtime.h>
#include <cuda_fp16.h>
#include <math.h>

#define Bdim 256
#define Ldim 256
#define Kdim 128
#define Hdim 256
#define NB   32
#define RPB  8
#define NTHR 512
#define IMP_SIZE (Bdim*Ldim*Kdim)   // 8388608

// smem row strides (floats)
#define SH 264     // hd, h, xc, u
#define XS 136     // xh
#define GS 776     // gh, gi

typedef unsigned long long ull;

// ---------------- static device scratch ----------------
// mma A-operand fragments, pre-swizzled in prep: one uint4 (4 x f16x2) per lane.
__device__ __align__(16) uint4 g_WAf [56*16*32];   // [x_h|gh] weights: M=896 (56 mt), K=256 (16 kt)
__device__ __align__(16) uint4 g_Wihf[48*8*32];    // W_ih c_c-half:    M=768 (48 mt), K=128 (8 kt)
__device__ __align__(16) uint4 g_Wff [8*8*32];     // W_feat zero-diag: M=128 (8 mt),  K=128 (8 kt)
__device__ __align__(16) float g_WihBT[128*768];   // W_ih mask-half^T fp32 (precompute)
__device__ __align__(16) float g_bA[896];          // [b_hist | b_hh]
__device__ __align__(16) float g_WT_gh[128*256];   // W_gh^T
__device__ __align__(16) float g_WT_comb[256*128]; // W_comb^T
__device__ float g_gxdiag[128];
__device__ float g_msum_inv[Ldim];
__device__ float g_loss_part[NB];
__device__ float g_deltas[Bdim*Ldim*Kdim];
__device__ float g_gammaH[Bdim*Ldim*Hdim];
__device__ float g_alpha [Bdim*Ldim*Kdim];
__device__ float g_gimask[(size_t)Bdim*Ldim*768];  // m @ W_ihB^T

// ---------------- helpers ----------------
__device__ __forceinline__ ull pk2(float a, float b){
    ull u; asm("mov.b64 %0,{%1,%2};" : "=l"(u) : "f"(a), "f"(b)); return u;
}
__device__ __forceinline__ float2 upk2(ull u){
    float2 f; asm("mov.b64 {%0,%1},%2;" : "=f"(f.x), "=f"(f.y) : "l"(u)); return f;
}
__device__ __forceinline__ void fma2(ull& d, ull a, ull b){
    asm("fma.rn.f32x2 %0,%1,%2,%0;" : "+l"(d) : "l"(a), "l"(b));
}
__device__ __forceinline__ unsigned pk16(float a, float b){
    __half2 h = __floats2half2_rn(a, b);      // .x = a (low), .y = b (high)
    return *reinterpret_cast<unsigned*>(&h);
}
// mma.m16n8k16 row.col f32 = f16*f16 + f32
__device__ __forceinline__ void mma16816(float& c0, float& c1, float& c2, float& c3,
                                         uint4 a, unsigned b0, unsigned b1){
    asm volatile("mma.sync.aligned.m16n8k16.row.col.f32.f16.f16.f32 "
                 "{%0,%1,%2,%3},{%4,%5,%6,%7},{%8,%9},{%0,%1,%2,%3};"
                 : "+f"(c0), "+f"(c1), "+f"(c2), "+f"(c3)
                 : "r"(a.x), "r"(a.y), "r"(a.z), "r"(a.w), "r"(b0), "r"(b1));
}
// Build B-fragment from fp32 smem src[n][k] (row stride S floats), k-base kb.
// b0 = {src[g][kb+t2], src[g][kb+t2+1]}, b1 = same at k+8.   (B col-major k16n8)
__device__ __forceinline__ void bfrag(const float* src, int S, int g, int t2, int kb,
                                      unsigned& b0, unsigned& b1){
    float2 p0 = *(const float2*)(src + g*S + kb + t2);
    float2 p1 = *(const float2*)(src + g*S + kb + t2 + 8);
    b0 = pk16(p0.x, p0.y);
    b1 = pk16(p1.x, p1.y);
}

// ---------------- fused precompute #1: prep + deltas + msum ----------------
__global__ void fused_pre1(const float* __restrict__ W_hist, const float* __restrict__ W_hh,
                           const float* __restrict__ b_hist, const float* __restrict__ b_hh,
                           const float* __restrict__ W_feat, const float* __restrict__ W_ih,
                           const float* __restrict__ W_gh,   const float* __restrict__ W_comb,
                           const float* __restrict__ W_gx,
                           const float* __restrict__ ts,     const float* __restrict__ mask,
                           const int*   __restrict__ record_num)
{
    __shared__ float sred[256];
    int bid = blockIdx.x;
    if (bid < 256){
        int tid = bid*256 + threadIdx.x;
        const int nt = 256*256;
        // A-fragments for [x_h | gh] GEMM
        for (int idx=tid; idx<56*16*32; idx+=nt){
            int mt = idx/512, rem = idx%512, kt = rem/32, l = rem%32;
            int g = l>>2, t2 = (l&3)*2;
            int o1 = mt*16+g, o2 = o1+8;
            int c1 = kt*16+t2, c2 = c1+8;
            #define WAval(o,k) ((o)<128 ? W_hist[(o)*256+(k)] : W_hh[((o)-128)*256+(k)])
            g_WAf[idx] = make_uint4(
                pk16(WAval(o1,c1), WAval(o1,c1+1)),
                pk16(WAval(o2,c1), WAval(o2,c1+1)),
                pk16(WAval(o1,c2), WAval(o1,c2+1)),
                pk16(WAval(o2,c2), WAval(o2,c2+1)));
            #undef WAval
        }
        // A-fragments for gi_cc GEMM (W_ih first 128 input cols)
        for (int idx=tid; idx<48*8*32; idx+=nt){
            int mt = idx/256, rem = idx%256, kt = rem/32, l = rem%32;
            int g = l>>2, t2 = (l&3)*2;
            int o1 = mt*16+g, o2 = o1+8;
            int c1 = kt*16+t2, c2 = c1+8;
            g_Wihf[idx] = make_uint4(
                pk16(W_ih[o1*256+c1], W_ih[o1*256+c1+1]),
                pk16(W_ih[o2*256+c1], W_ih[o2*256+c1+1]),
                pk16(W_ih[o1*256+c2], W_ih[o1*256+c2+1]),
                pk16(W_ih[o2*256+c2], W_ih[o2*256+c2+1]));
        }
        // A-fragments for z_h GEMM (W_feat, zero diag)
        for (int idx=tid; idx<8*8*32; idx+=nt){
            int mt = idx/256, rem = idx%256, kt = rem/32, l = rem%32;
            int g = l>>2, t2 = (l&3)*2;
            int o1 = mt*16+g, o2 = o1+8;
            int c1 = kt*16+t2, c2 = c1+8;
            #define WFval(o,k) ((o)==(k) ? 0.f : W_feat[(o)*128+(k)])
            g_Wff[idx] = make_uint4(
                pk16(WFval(o1,c1), WFval(o1,c1+1)),
                pk16(WFval(o2,c1), WFval(o2,c1+1)),
                pk16(WFval(o1,c2), WFval(o1,c2+1)),
                pk16(WFval(o2,c2), WFval(o2,c2+1)));
            #undef WFval
        }
        for (int idx=tid; idx<896; idx+=nt)
            g_bA[idx] = (idx<128) ? b_hist[idx] : b_hh[idx-128];
        for (int idx=tid; idx<128*768; idx+=nt){
            int k=idx/768, o=idx%768;
            g_WihBT[idx] = W_ih[o*256 + 128 + k];
        }
        for (int idx=tid; idx<128*256; idx+=nt){
            int i=idx>>8, o=idx&255;
            g_WT_gh[idx] = W_gh[o*128+i];
        }
        for (int idx=tid; idx<256*128; idx+=nt){
            int j=idx>>7, o=idx&127;
            g_WT_comb[idx] = W_comb[o*256+j];
        }
        for (int idx=tid; idx<128; idx+=nt) g_gxdiag[idx] = W_gx[idx*128+idx];
    } else if (bid < 512){
        if (threadIdx.x >= 128) return;
        int b = bid - 256;
        int k = threadIdx.x;
        int rec = record_num[b];
        const float* tsb = ts + b*Ldim;
        float d = 1.f;
        float tsp = tsb[0];
        g_deltas[(b*Ldim+0)*Kdim + k] = (0 < rec) ? 1.f : 0.f;
        for (int t0=1; t0<Ldim; t0+=5){
            float mv[5], tv[5];
            #pragma unroll
            for (int j=0;j<5;j++){
                mv[j] = mask[(b*Ldim+t0+j)*Kdim + k];
                tv[j] = tsb[t0+j];
            }
            #pragma unroll
            for (int j=0;j<5;j++){
                d = fabsf(tv[j]-tsp) + (1.f-mv[j])*d;
                tsp = tv[j];
                g_deltas[(b*Ldim+t0+j)*Kdim + k] = (t0+j < rec) ? d : 0.f;
            }
        }
    } else {
        int t = bid - 512;
        float sm = 0.f;
        for (int idx=threadIdx.x; idx<Bdim*Kdim; idx+=256){
            int b = idx>>7, k = idx&127;
            sm += mask[(b*Ldim+t)*Kdim + k];
        }
        sred[threadIdx.x] = sm; __syncthreads();
        for (int st=128; st>0; st>>=1){ if (threadIdx.x<st) sred[threadIdx.x]+=sred[threadIdx.x+st]; __syncthreads(); }
        if (threadIdx.x==0) g_msum_inv[t] = 1.f/(sred[0] + 1e-5f);
    }
}

// ---------------- fused precompute #2: gammaH + alpha + gimask (unchanged) ----------------
__global__ void fused_pre2(const float* __restrict__ mask,
                           const float* __restrict__ b_gh,
                           const float* __restrict__ b_gx, const float* __restrict__ b_comb)
{
    __shared__ __align__(16) float sbuf[256*18];
    int bid = blockIdx.x;
    if (bid < 4096){
        float (*sd)[18] = (float(*)[18])sbuf;
        int row0 = bid*16;
        for (int idx=threadIdx.x; idx<16*128; idx+=256){
            int r = idx>>7, i = idx&127;
            sd[i][r] = g_deltas[(row0+r)*Kdim + i];
        }
        __syncthreads();
        int o = threadIdx.x;
        ull acc[8];
        #pragma unroll
        for (int j=0;j<8;j++) acc[j]=0ull;
        #pragma unroll 4
        for (int i=0;i<128;i++){
            float w = g_WT_gh[i*256 + o];
            ull w2 = pk2(w, w);
            #pragma unroll
            for (int j=0;j<8;j++){
                ull sp = *(const ull*)(&sd[i][2*j]);
                fma2(acc[j], w2, sp);
            }
        }
        float bv = b_gh[o];
        #pragma unroll
        for (int j=0;j<8;j++){
            float2 a = upk2(acc[j]);
            g_gammaH[(row0+2*j  )*Hdim + o] = __expf(-fmaxf(a.x+bv, 0.f));
            g_gammaH[(row0+2*j+1)*Hdim + o] = __expf(-fmaxf(a.y+bv, 0.f));
        }
    } else if (bid < 8192){
        float (*su)[18] = (float(*)[18])sbuf;
        int row0 = (bid-4096)*16;
        for (int idx=threadIdx.x; idx<16*128; idx+=256){
            int r = idx>>7, k = idx&127;
            float d = g_deltas[(row0+r)*Kdim + k];
            su[k][r]     = __expf(-fmaxf(d*g_gxdiag[k] + b_gx[k], 0.f));
            su[128+k][r] = mask[(row0+r)*Kdim + k];
        }
        __syncthreads();
        int o  = threadIdx.x & 127;
        int rh = threadIdx.x >> 7;
        ull acc[4];
        #pragma unroll
        for (int j=0;j<4;j++) acc[j]=0ull;
        #pragma unroll 4
        for (int i=0;i<256;i++){
            float w = g_WT_comb[i*128 + o];
            ull w2 = pk2(w, w);
            #pragma unroll
            for (int j=0;j<4;j++){
                ull sp = *(const ull*)(&su[i][rh*8 + 2*j]);
                fma2(acc[j], w2, sp);
            }
        }
        float bc = b_comb[o];
        #pragma unroll
        for (int j=0;j<4;j++){
            float2 a = upk2(acc[j]);
            g_alpha[(row0+rh*8+2*j  )*Kdim + o] = a.x + bc;
            g_alpha[(row0+rh*8+2*j+1)*Kdim + o] = a.y + bc;
        }
    } else {
        float (*sm)[18] = (float(*)[18])sbuf;
        int row0 = (bid-8192)*16;
        for (int idx=threadIdx.x; idx<16*128; idx+=256){
            int r = idx>>7, k = idx&127;
            sm[k][r] = mask[(row0+r)*Kdim + k];
        }
        __syncthreads();
        #pragma unroll
        for (int pass=0; pass<3; pass++){
            int o = pass*256 + threadIdx.x;
            ull acc[8];
            #pragma unroll
            for (int j=0;j<8;j++) acc[j]=0ull;
            #pragma unroll 4
            for (int k=0;k<128;k++){
                float w = g_WihBT[k*768 + o];
                ull w2 = pk2(w, w);
                #pragma unroll
                for (int j=0;j<8;j++){
                    ull sp = *(const ull*)(&sm[k][2*j]);
                    fma2(acc[j], w2, sp);
                }
            }
            #pragma unroll
            for (int j=0;j<8;j++){
                float2 a = upk2(acc[j]);
                g_gimask[(size_t)(row0+2*j  )*768 + o] = a.x;
                g_gimask[(size_t)(row0+2*j+1)*768 + o] = a.y;
            }
        }
    }
}

__global__ void dummy_kernel(){}

// ---------------- main recurrent kernel (mma, RPB=8, NB=32) ----------------
struct SMem {
    float hd[8*SH];
    float h [8*SH];
    float xc[8*SH];
    float u [8*SH];
    float xh[8*XS];
    float gh[8*GS];
    float gi[8*GS];
    float bufx[2][8*128];
    float bufm[2][8*128];
    float bufa[2][8*128];
    float bufg[2][8*256];
    float bufgi[2][8*768];
    float bufe[2][8];
    float sbA[896];
    float sbih[768];
    float sbf[128];
    float sWout[256];
    float sinv[256];
    float red[NTHR];
};

__global__ __launch_bounds__(NTHR, 1) void rits_main(
    const float* __restrict__ x, const float* __restrict__ mask, const float* __restrict__ ts,
    const float* __restrict__ b_feat, const float* __restrict__ b_ih,
    const float* __restrict__ W_out,  const float* __restrict__ b_out,
    float* __restrict__ out)
{
    extern __shared__ char smem_raw[];
    SMem* s = (SMem*)smem_raw;

    const int tid = threadIdx.x;
    const int w   = tid >> 5;
    const int l   = tid & 31;
    const int g   = l >> 2;
    const int t2  = (l & 3)*2;
    const int r0  = blockIdx.x * RPB;

    auto prefetch = [&](int tt, int buf, int pid, int np){
        #pragma unroll
        for (int n=0; n<8; n++){
            const float4* px = (const float4*)(x      + ((size_t)(r0+n)*Ldim + tt)*Kdim);
            const float4* pm = (const float4*)(mask   + ((size_t)(r0+n)*Ldim + tt)*Kdim);
            const float4* pa = (const float4*)(g_alpha+ ((size_t)(r0+n)*Ldim + tt)*Kdim);
            for (int v=pid; v<32; v+=np){
                ((float4*)&s->bufx[buf][n*128])[v] = px[v];
                ((float4*)&s->bufm[buf][n*128])[v] = pm[v];
                ((float4*)&s->bufa[buf][n*128])[v] = pa[v];
            }
            const float4* pg = (const float4*)(g_gammaH + (size_t)((r0+n)*Ldim + tt)*Hdim);
            for (int v=pid; v<64; v+=np)
                ((float4*)&s->bufg[buf][n*256])[v] = pg[v];
            const float4* pq = (const float4*)(g_gimask + (size_t)((r0+n)*Ldim + tt)*768);
            for (int v=pid; v<192; v+=np)
                ((float4*)&s->bufgi[buf][n*768])[v] = pq[v];
        }
        if (pid < 8) s->bufe[buf][pid] = (ts[(size_t)(r0+pid)*Ldim + tt] != 0.f) ? 1.f : 0.f;
    };

    // one-time init
    for (int idx=tid; idx<896; idx+=NTHR) s->sbA[idx]  = g_bA[idx];
    for (int idx=tid; idx<768; idx+=NTHR) s->sbih[idx] = b_ih[idx];
    for (int idx=tid; idx<128; idx+=NTHR) s->sbf[idx]  = b_feat[idx];
    for (int idx=tid; idx<256; idx+=NTHR){ s->sWout[idx] = W_out[idx]; s->sinv[idx] = g_msum_inv[idx]; }
    for (int idx=tid; idx<8*SH; idx+=NTHR){ s->hd[idx] = 0.f; s->h[idx] = 0.f; }
    prefetch(0, 0, tid, NTHR);
    float loss = 0.f;
    int cur = 0;
    __syncthreads();

    for (int t=0; t<Ldim; t++){
        const int nxt = cur ^ 1;

        // ---- phase A: [x_h | gh] = hd @ WA + bias  (mma; warps 0-13, 4 M-tiles each) ----
        if (w < 14){
            float c[4][4] = {{0.f,0.f,0.f,0.f},{0.f,0.f,0.f,0.f},{0.f,0.f,0.f,0.f},{0.f,0.f,0.f,0.f}};
            #pragma unroll
            for (int kt=0; kt<16; kt++){
                unsigned b0, b1;
                bfrag(s->hd, SH, g, t2, kt*16, b0, b1);
                #pragma unroll
                for (int j=0; j<4; j++){
                    uint4 a = g_WAf[((w*4+j)*16 + kt)*32 + l];
                    mma16816(c[j][0], c[j][1], c[j][2], c[j][3], a, b0, b1);
                }
            }
            #pragma unroll
            for (int j=0; j<4; j++){
                int mt = w*4+j;
                int o1 = mt*16+g, o2 = o1+8;
                float ba1 = s->sbA[o1], ba2 = s->sbA[o2];
                if (mt < 8){
                    s->xh[t2*XS + o1]     = c[j][0]+ba1;
                    s->xh[(t2+1)*XS + o1] = c[j][1]+ba1;
                    s->xh[t2*XS + o2]     = c[j][2]+ba2;
                    s->xh[(t2+1)*XS + o2] = c[j][3]+ba2;
                } else {
                    int q1 = o1-128, q2 = o2-128;
                    s->gh[t2*GS + q1]     = c[j][0]+ba1;
                    s->gh[(t2+1)*GS + q1] = c[j][1]+ba1;
                    s->gh[t2*GS + q2]     = c[j][2]+ba2;
                    s->gh[(t2+1)*GS + q2] = c[j][3]+ba2;
                }
            }
        } else if (t+1 < Ldim){
            prefetch(t+1, nxt, tid-448, 64);
        }
        __syncthreads();

        // ---- phase B: x_c ----
        #pragma unroll
        for (int q=0; q<2; q++){
            int i = tid*2+q;
            int n = i>>7, k = i&127;
            float mv = s->bufm[cur][n*128+k];
            s->xc[n*SH+k] = mv*s->bufx[cur][n*128+k] + (1.f-mv)*s->xh[n*XS+k];
        }
        __syncthreads();

        // ---- phase C: z_h = xc @ W_feat (mma; warps 0-7) + in-register epilogue ----
        if (w < 8){
            float c[4] = {0.f,0.f,0.f,0.f};
            #pragma unroll
            for (int kt=0; kt<8; kt++){
                unsigned b0, b1;
                bfrag(s->xc, SH, g, t2, kt*16, b0, b1);
                uint4 a = g_Wff[(w*8+kt)*32 + l];
                mma16816(c[0], c[1], c[2], c[3], a, b0, b1);
            }
            float inv = s->sinv[t];
            #pragma unroll
            for (int half=0; half<2; half++){
                int k = w*16 + g + half*8;
                float bf = s->sbf[k];
                #pragma unroll
                for (int dn=0; dn<2; dn++){
                    int n = t2+dn;
                    float zh = c[half*2+dn] + bf;
                    float xv = s->bufx[cur][n*128+k];
                    float mv = s->bufm[cur][n*128+k];
                    float xhv = s->xh[n*XS+k];
                    float al = s->bufa[cur][n*128+k];
                    float e  = s->bufe[cur][n];
                    float ch = al*zh + (1.f-al)*xhv;
                    float cc = mv*xv + (1.f-mv)*ch;
                    loss += (fabsf(xv-xhv)*mv + (fabsf(xv-zh)+fabsf(xv-ch))*mv*e)*inv;
                    s->u[n*SH+k] = cc;
                    out[((size_t)(r0+n)*Ldim + t)*Kdim + k] = cc*e;
                }
            }
        }
        __syncthreads();

        // ---- phase D: gi_cc = c_c @ W_ihA + b_ih (mma; all 16 warps, 3 M-tiles each) ----
        {
            float c[3][4] = {{0.f,0.f,0.f,0.f},{0.f,0.f,0.f,0.f},{0.f,0.f,0.f,0.f}};
            #pragma unroll
            for (int kt=0; kt<8; kt++){
                unsigned b0, b1;
                bfrag(s->u, SH, g, t2, kt*16, b0, b1);
                #pragma unroll
                for (int j=0; j<3; j++){
                    uint4 a = g_Wihf[((w*3+j)*8 + kt)*32 + l];
                    mma16816(c[j][0], c[j][1], c[j][2], c[j][3], a, b0, b1);
                }
            }
            #pragma unroll
            for (int j=0; j<3; j++){
                int mt = w*3+j;
                int o1 = mt*16+g, o2 = o1+8;
                float bi1 = s->sbih[o1], bi2 = s->sbih[o2];
                s->gi[t2*GS + o1]     = c[j][0]+bi1;
                s->gi[(t2+1)*GS + o1] = c[j][1]+bi1;
                s->gi[t2*GS + o2]     = c[j][2]+bi2;
                s->gi[(t2+1)*GS + o2] = c[j][3]+bi2;
            }
        }
        __syncthreads();

        // ---- phase E: GRU gates + e-blend + next-step decay ----
        #pragma unroll
        for (int q=0; q<4; q++){
            int idx = tid + q*NTHR;
            int r = idx>>8, o = idx&255;
            float gr = s->gi[r*GS+o]     + s->bufgi[cur][r*768+o];
            float gz = s->gi[r*GS+256+o] + s->bufgi[cur][r*768+256+o];
            float gn = s->gi[r*GS+512+o] + s->bufgi[cur][r*768+512+o];
            float rg = 1.f/(1.f + __expf(-(gr + s->gh[r*GS+o])));
            float zg = 1.f/(1.f + __expf(-(gz + s->gh[r*GS+256+o])));
            float targ = gn + rg*s->gh[r*GS+512+o];
            float ex = __expf(-2.f*targ);
            float ng = (1.f - ex)/(1.f + ex);
            float hdv = s->hd[r*SH+o];
            float hn = (1.f-zg)*ng + zg*hdv;
            float e  = s->bufe[cur][r];
            float hnew = hn*e + (1.f-e)*s->h[r*SH+o];
            s->h[r*SH+o] = hnew;
            if (t+1 < Ldim) s->hd[r*SH+o] = hnew * s->bufg[nxt][r*256+o];
        }
        cur = nxt;
        __syncthreads();
    }

    // ---- predictions ----
    for (int r=0; r<RPB; r++){
        s->red[tid] = (tid < 256) ? s->h[r*SH+tid]*s->sWout[tid] : 0.f;
        __syncthreads();
        for (int st=NTHR/2; st>0; st>>=1){ if (tid<st) s->red[tid]+=s->red[tid+st]; __syncthreads(); }
        if (tid==0) out[IMP_SIZE + 1 + r0 + r] = 1.f/(1.f + __expf(-(s->red[0] + b_out[0])));
        __syncthreads();
    }

    // ---- per-block loss partial ----
    s->red[tid] = loss; __syncthreads();
    for (int st=NTHR/2; st>0; st>>=1){ if (tid<st) s->red[tid]+=s->red[tid+st]; __syncthreads(); }
    if (tid==0) g_loss_part[blockIdx.x] = s->red[0];
}

// ---------------- deterministic loss reduction ----------------
__global__ void finalize_kernel(float* __restrict__ out)
{
    if (threadIdx.x==0 && blockIdx.x==0){
        float sum = 0.f;
        for (int i=0;i<NB;i++) sum += g_loss_part[i];
        out[IMP_SIZE] = sum;
    }
}

// ---------------- launch ----------------
extern "C" void kernel_launch(void* const* d_in, const int* in_sizes, int n_in,
                              void* d_out, int out_size)
{
    const float* x      = (const float*)d_in[0];
    const float* mask   = (const float*)d_in[1];
    const float* ts     = (const float*)d_in[2];
    const float* W_gh   = (const float*)d_in[3];
    const float* b_gh   = (const float*)d_in[4];
    const float* W_gx   = (const float*)d_in[5];
    const float* b_gx   = (const float*)d_in[6];
    const float* W_hist = (const float*)d_in[7];
    const float* b_hist = (const float*)d_in[8];
    const float* W_feat = (const float*)d_in[9];
    const float* b_feat = (const float*)d_in[10];
    const float* W_comb = (const float*)d_in[11];
    const float* b_comb = (const float*)d_in[12];
    const float* W_ih   = (const float*)d_in[13];
    const float* W_hh   = (const float*)d_in[14];
    const float* b_ih   = (const float*)d_in[15];
    const float* b_hh   = (const float*)d_in[16];
    const float* W_out  = (const float*)d_in[17];
    const float* b_out  = (const float*)d_in[18];
    const int*   recnum = (const int*)  d_in[19];
    float* out = (float*)d_out;

    static int smem_set = 0;
    const int SMEM_BYTES = (int)sizeof(SMem);
    if (!smem_set){
        cudaFuncSetAttribute(rits_main, cudaFuncAttributeMaxDynamicSharedMemorySize, SMEM_BYTES);
        smem_set = 1;
    }

    fused_pre1<<<768, 256>>>(W_hist, W_hh, b_hist, b_hh, W_feat, W_ih, W_gh, W_comb, W_gx,
                             ts, mask, recnum);
    fused_pre2<<<12288, 256>>>(mask, b_gh, b_gx, b_comb);
    dummy_kernel<<<1, 32>>>();
    rits_main<<<NB, NTHR, SMEM_BYTES>>>(x, mask, ts, b_feat, b_ih, W_out, b_out, out);
    finalize_kernel<<<1, 32>>>(out);
}